// round 4
// baseline (speedup 1.0000x reference)
#include <cuda_runtime.h>

#define NUM_FACES 13776
#define MAXC 8
#define EPSF 1e-8f
#define SIGMA 0.5f
#define GRID 148
#define TPB 1024
#define NWARPS (GRID * (TPB / 32))   // 4736 warps

// ---- device scratch (static zero-init; no runtime allocations) ----
__device__ float4 g_bbmin[NUM_FACES];   // (minx,miny,minz, face_id0 bits)
__device__ float4 g_bbmax[NUM_FACES];   // (maxx,maxy,maxz, face_id1 bits)
__device__ int    g_f2[NUM_FACES];      // face_id2
__device__ float  g_tri[NUM_FACES * 9]; // 3 verts x 3 coords per face
__device__ double g_accum;              // self-resetting accumulator
__device__ unsigned g_bar_count;        // grid barrier arrivals
__device__ volatile unsigned g_bar_sense;
__device__ unsigned g_done;             // epilogue arrivals

// Sense-reversing grid barrier. Safe because grid = 148 blocks of 1024
// threads at 1 block/SM: wave-1 CTA placement covers all 148 SMs, so every
// block is resident while spinning. State self-resets each use.
__device__ __forceinline__ void grid_barrier() {
    __threadfence();
    __syncthreads();
    if (threadIdx.x == 0) {
        unsigned s = g_bar_sense;
        unsigned old = atomicAdd(&g_bar_count, 1u);
        if (old == GRID - 1) {
            g_bar_count = 0;            // reset for next launch/use
            __threadfence();
            g_bar_sense = s ^ 1u;       // release
        } else {
            while (g_bar_sense == s) { }
        }
        __threadfence();
    }
    __syncthreads();
}

// ---------------------------------------------------------------------------
// Cone-field penalty of src triangle evaluated at the 3 verts of pts tri.
// Mirrors reference math exactly (float32, PENALIZE_OUTSIDE, phi^2).
// ---------------------------------------------------------------------------
__device__ __forceinline__ float cone_penalty(const float* __restrict__ A,
                                              const float* __restrict__ P) {
    float a0x = A[0], a0y = A[1], a0z = A[2];
    float a1x = A[3], a1y = A[4], a1z = A[5];
    float a2x = A[6], a2y = A[7], a2z = A[8];

    float e0x = a1x - a0x, e0y = a1y - a0y, e0z = a1z - a0z;
    float e1x = a2x - a0x, e1y = a2y - a0y, e1z = a2z - a0z;

    float nx = e0y * e1z - e0z * e1y;
    float ny = e0z * e1x - e0x * e1z;
    float nz = e0x * e1y - e0y * e1x;
    float nn = sqrtf(nx * nx + ny * ny + nz * nz);
    float inv = 1.0f / (nn + EPSF);
    nx *= inv; ny *= inv; nz *= inv;

    float cx = (a0x + a1x + a2x) * (1.0f / 3.0f);
    float cy = (a0y + a1y + a2y) * (1.0f / 3.0f);
    float cz = (a0z + a1z + a2z) * (1.0f / 3.0f);

    float pen = 0.0f;
#pragma unroll
    for (int v = 0; v < 3; v++) {
        float ux = P[3 * v + 0] - cx;
        float uy = P[3 * v + 1] - cy;
        float uz = P[3 * v + 2] - cz;
        float h = ux * nx + uy * ny + uz * nz;
        float wx = ux - h * nx;
        float wy = uy - h * ny;
        float wz = uz - h * nz;
        float r = sqrtf(wx * wx + wy * wy + wz * wz);
        float radial = fmaxf(1.0f - r / SIGMA, 0.0f);
        float depth = fmaxf(-h, 0.0f) + fmaxf(h, 0.0f) * expf(-h / SIGMA);
        float phi = radial * depth;
        pen += phi * phi;
    }
    return pen;
}

// ---------------------------------------------------------------------------
// ONE persistent kernel: setup -> grid barrier -> collide -> epilogue.
// ---------------------------------------------------------------------------
__global__ void __launch_bounds__(TPB, 1)
fused_kernel(const float* __restrict__ verts,
             const int*   __restrict__ faces,
             float*       __restrict__ out) {
    __shared__ int    s_list[TPB / 32][MAXC];
    __shared__ double s_bsum;

    int tid = threadIdx.x;
    if (tid == 0) s_bsum = 0.0;

    // ---------- Phase 1: setup, 4 lanes per face, spread across all blocks --
    {
        int group = tid >> 2;                        // 0..255
        int l = tid & 3;
        int f = group * GRID + blockIdx.x;           // every block active
        int fc = (f < NUM_FACES) ? f : (NUM_FACES - 1);  // clamp: keep shuffles converged
        int comp = (l < 2) ? l : 2;                  // lane 3 duplicates lane 2
        int idx = faces[3 * fc + comp];
        float x = verts[3 * idx + 0];
        float y = verts[3 * idx + 1];
        float z = verts[3 * idx + 2];

        if (f < NUM_FACES && l < 3) {
            g_tri[f * 9 + 3 * l + 0] = x;
            g_tri[f * 9 + 3 * l + 1] = y;
            g_tri[f * 9 + 3 * l + 2] = z;
        }

        float mnx = x, mny = y, mnz = z, mxx = x, mxy = y, mxz = z;
#pragma unroll
        for (int off = 1; off <= 2; off <<= 1) {
            mnx = fminf(mnx, __shfl_xor_sync(0xffffffffu, mnx, off));
            mny = fminf(mny, __shfl_xor_sync(0xffffffffu, mny, off));
            mnz = fminf(mnz, __shfl_xor_sync(0xffffffffu, mnz, off));
            mxx = fmaxf(mxx, __shfl_xor_sync(0xffffffffu, mxx, off));
            mxy = fmaxf(mxy, __shfl_xor_sync(0xffffffffu, mxy, off));
            mxz = fmaxf(mxz, __shfl_xor_sync(0xffffffffu, mxz, off));
        }
        int i1 = __shfl_xor_sync(0xffffffffu, idx, 1);  // lane0 <- lane1's idx
        int i2 = __shfl_xor_sync(0xffffffffu, idx, 2);  // lane0 <- lane2's idx

        if (f < NUM_FACES && l == 0) {
            g_bbmin[f] = make_float4(mnx, mny, mnz, __int_as_float(idx));  // i0
            g_bbmax[f] = make_float4(mxx, mxy, mxz, __int_as_float(i1));
            g_f2[f]    = i2;
        }
    }

    // ---------- Grid barrier: all AABBs/triangles visible device-wide ------
    grid_barrier();

    // ---------- Phase 2: warp-per-row ordered scan + narrow phase ----------
    int lane = tid & 31;
    int wwid = tid >> 5;
    double mysum = 0.0;

    for (int row = blockIdx.x * (TPB / 32) + wwid; row < NUM_FACES; row += NWARPS) {
        float4 bmin = g_bbmin[row];
        float4 bmax = g_bbmax[row];
        int rf0 = __float_as_int(bmin.w);
        int rf1 = __float_as_int(bmax.w);
        int rf2 = g_f2[row];

        // first MAXC valid j ascending (== stable top_k over 0/1 matrix)
        int found = 0;
        for (int base = 0; base < NUM_FACES && found < MAXC; base += 32) {
            int j = base + lane;
            bool ok = false;
            if (j < NUM_FACES) {
                float4 jmin = g_bbmin[j];
                float4 jmax = g_bbmax[j];
                ok = (bmin.x <= jmax.x) && (jmin.x <= bmax.x) &&
                     (bmin.y <= jmax.y) && (jmin.y <= bmax.y) &&
                     (bmin.z <= jmax.z) && (jmin.z <= bmax.z);
                if (ok) {
                    int jf0 = __float_as_int(jmin.w);
                    int jf1 = __float_as_int(jmax.w);
                    int jf2 = g_f2[j];
                    bool share = (rf0 == jf0) | (rf0 == jf1) | (rf0 == jf2) |
                                 (rf1 == jf0) | (rf1 == jf1) | (rf1 == jf2) |
                                 (rf2 == jf0) | (rf2 == jf1) | (rf2 == jf2);
                    ok = !share;
                }
            }
            unsigned m = __ballot_sync(0xffffffffu, ok);
            int rank = found + __popc(m & ((1u << lane) - 1u));
            if (ok && rank < MAXC) s_list[wwid][rank] = j;
            found += __popc(m);
        }
        if (found > MAXC) found = MAXC;
        __syncwarp();

        // narrow phase: lanes 0..15 -> (pair 0..7) x (direction 0..1)
        float pen = 0.0f;
        int pairIdx = lane >> 1;
        int dir = lane & 1;
        if (lane < 16 && pairIdx < found) {
            int jrow = s_list[wwid][pairIdx];
            const float* src = &g_tri[(dir ? jrow : row) * 9];
            const float* pts = &g_tri[(dir ? row : jrow) * 9];
            pen = cone_penalty(src, pts);
        }
#pragma unroll
        for (int off = 16; off > 0; off >>= 1)
            pen += __shfl_xor_sync(0xffffffffu, pen, off);

        mysum += (double)pen;
        __syncwarp();   // s_list reuse next row iteration
    }

    if (lane == 0 && mysum != 0.0) atomicAdd(&s_bsum, mysum);
    __syncthreads();

    // ---------- Epilogue: last-arriving block writes output, resets state --
    if (tid == 0) {
        if (s_bsum != 0.0) atomicAdd(&g_accum, s_bsum);
        __threadfence();
        unsigned old = atomicAdd(&g_done, 1u);
        if (old == GRID - 1) {
            g_done = 0;                                    // reset for replay
            unsigned long long bits =
                atomicExch((unsigned long long*)&g_accum, 0ULL);  // read + reset
            out[0] = (float)__longlong_as_double(bits);    // COLL_LOSS_WEIGHT = 1
        }
    }
}

extern "C" void kernel_launch(void* const* d_in, const int* in_sizes, int n_in,
                              void* d_out, int out_size) {
    const float* verts = (const float*)d_in[0];
    const int*   faces = (const int*)d_in[1];
    float*       out   = (float*)d_out;

    fused_kernel<<<GRID, TPB>>>(verts, faces, out);
}